// round 13
// baseline (speedup 1.0000x reference)
#include <cuda_runtime.h>
#include <cstdint>

// ---------------------------------------------------------------------------
// TripletFeatures: M=41, p=20.  Index set: |m*n|<=20, n>=m, |m|+|n|<=20, K=173.
// out[b,c,k] = Re( S_mn * E[p+n,c] ) + (m!=n) * Re( S_nm * E[p+m,c] )
//   with S_xy = sum_c E[p+x,c]*conj(E[p+x+y,c])
// Output contract (verified): float32 (B, 2, K), REAL PART ONLY.
//
// Champion skeleton (1 warp/batch, constexpr table, coalesced stores,
// warp-sync only) + PAIRED-k processing: each lane handles (2p, 2p+1).
// m-major order => most pairs share u, so the second U load is predicated
// away; table reads halve; component-0 stores become STG.64.
// ---------------------------------------------------------------------------

constexpr int K    = 173;
constexpr int WPB  = 8;     // warps (batches) per block
constexpr int ME   = 82;    // floats per batch per input array (41 pos * 2 c)
constexpr int PLN  = 48;    // padded plane stride (float2 units)
constexpr int NPAIR = 87;   // ceil(173/2); pair 86 has only k=172 valid

struct PT { unsigned e[96]; };   // u1 | v1<<8 | u2<<16 | v2<<24

__host__ __device__ constexpr PT make_pt() {
    unsigned short raw[174] = {};
    int cnt = 0;
    for (int m = -20; m <= 20; ++m) {
        for (int n = -20; n <= 20; ++n) {
            int am = m < 0 ? -m : m;
            int an = n < 0 ? -n : n;
            if (am * an <= 20 && n >= m && am + an <= 20) {
                raw[cnt] = (unsigned short)((m + 20) | ((n + 20) << 8));
                ++cnt;
            }
        }
    }
    raw[173] = raw[172];   // harmless duplicate; its store is guarded off
    PT t{};
    for (int p = 0; p < 96; ++p) {
        const int k1 = 2 * p;
        if (k1 < 173)
            t.e[p] = (unsigned)raw[k1] | ((unsigned)raw[k1 + 1] << 16);
        else
            t.e[p] = 0;
    }
    return t;
}

__global__ void __launch_bounds__(WPB * 32, 4)
triplet_kernel(const float* __restrict__ er,
               const float* __restrict__ ei,
               float* __restrict__ out,
               int B)
{
    static constexpr PT TAB = make_pt();

    // Component planes: plane c holds (re, im) of E[pos, c]; class = pos mod 16.
    __shared__ float2 Esh[WPB][2 * PLN];

    const int w    = threadIdx.x >> 5;
    const int lane = threadIdx.x & 31;
    const long long b = (long long)blockIdx.x * WPB + w;
    if (b >= B) return;

    // Stage this warp's batch (coalesced; input float index j = 2*pos + c).
    const float* rbase = er + b * ME;
    const float* ibase = ei + b * ME;
    #pragma unroll
    for (int j = lane; j < ME; j += 32) {
        const int pos = j >> 1;
        const int c   = j & 1;
        Esh[w][c * PLN + pos] = make_float2(rbase[j], ibase[j]);
    }
    __syncwarp();

    const float2* E0 = Esh[w];         // component 0 plane
    const float2* E1 = Esh[w] + PLN;   // component 1 plane
    float*  ob  = out + b * (2 * K);   // component 0 row (8B-aligned base)
    float2* ob2 = reinterpret_cast<float2*>(ob);
    float*  obK = ob + K;              // component 1 row (odd float offset)

    #pragma unroll
    for (int i = 0; i < 3; ++i) {
        const int p = lane + 32 * i;
        if (i < 2 || p < NPAIR) {
            const unsigned e = TAB.e[p];
            const int u1 = e & 0xff;
            const int v1 = (e >> 8) & 0xff;
            const int u2 = (e >> 16) & 0xff;
            const int v2 = e >> 24;
            const int w1 = u1 + v1 - 20;
            const int w2 = u2 + v2 - 20;

            // ---- k1 = 2p ----
            const float2 U0a = E0[u1], U1a = E1[u1];
            const float2 V0a = E0[v1], V1a = E1[v1];
            const float2 W0a = E0[w1], W1a = E1[w1];

            const float Sra = U0a.x*W0a.x + U0a.y*W0a.y + U1a.x*W1a.x + U1a.y*W1a.y;
            const float Sia = U0a.y*W0a.x - U0a.x*W0a.y + U1a.y*W1a.x - U1a.x*W1a.y;
            float o0a = Sra * V0a.x - Sia * V0a.y;
            float o1a = Sra * V1a.x - Sia * V1a.y;
            if (u1 != v1) {
                const float Tr = V0a.x*W0a.x + V0a.y*W0a.y + V1a.x*W1a.x + V1a.y*W1a.y;
                const float Ti = V0a.y*W0a.x - V0a.x*W0a.y + V1a.y*W1a.x - V1a.x*W1a.y;
                o0a += Tr * U0a.x - Ti * U0a.y;
                o1a += Tr * U1a.x - Ti * U1a.y;
            }

            // ---- k2 = 2p+1 (U reloaded only across m-run boundaries) ----
            float2 U0b = U0a, U1b = U1a;
            if (u2 != u1) { U0b = E0[u2]; U1b = E1[u2]; }
            const float2 V0b = E0[v2], V1b = E1[v2];
            const float2 W0b = E0[w2], W1b = E1[w2];

            const float Srb = U0b.x*W0b.x + U0b.y*W0b.y + U1b.x*W1b.x + U1b.y*W1b.y;
            const float Sib = U0b.y*W0b.x - U0b.x*W0b.y + U1b.y*W1b.x - U1b.x*W1b.y;
            float o0b = Srb * V0b.x - Sib * V0b.y;
            float o1b = Srb * V1b.x - Sib * V1b.y;
            if (u2 != v2) {
                const float Tr = V0b.x*W0b.x + V0b.y*W0b.y + V1b.x*W1b.x + V1b.y*W1b.y;
                const float Ti = V0b.y*W0b.x - V0b.x*W0b.y + V1b.y*W1b.x - V1b.x*W1b.y;
                o0b += Tr * U0b.x - Ti * U0b.y;
                o1b += Tr * U1b.x - Ti * U1b.y;
            }

            // ---- stores ----
            const int k1 = 2 * p;
            if (k1 + 1 < K) {
                ob2[p] = make_float2(o0a, o0b);   // out[b,0,k1], out[b,0,k1+1]
                obK[k1]     = o1a;                // out[b,1,k1]
                obK[k1 + 1] = o1b;                // out[b,1,k1+1]
            } else {                              // p == 86: only k=172 valid
                ob[k1]  = o0a;
                obK[k1] = o1a;
            }
        }
    }
}

extern "C" void kernel_launch(void* const* d_in, const int* in_sizes, int n_in,
                              void* d_out, int out_size)
{
    const float* er = (const float*)d_in[0];   // E_real (B, 41, 2) float32
    const float* ei = (const float*)d_in[1];   // E_imag (B, 41, 2) float32
    float* out = (float*)d_out;                // float32 (B, 2, K) real parts

    const int B = in_sizes[0] / ME;
    const int grid = (B + WPB - 1) / WPB;

    triplet_kernel<<<grid, WPB * 32>>>(er, ei, out, B);
}

// round 14
// speedup vs baseline: 1.1233x; 1.1233x over previous
#include <cuda_runtime.h>
#include <cuda_fp16.h>
#include <cstdint>

// ---------------------------------------------------------------------------
// TripletFeatures: M=41, p=20.  Index set: |m*n|<=20, n>=m, |m|+|n|<=20, K=173.
// out[b,c,k] = Re( S_mn * E[p+n,c] ) + (m!=n) * Re( S_nm * E[p+m,c] )
//   with S_xy = sum_c E[p+x,c]*conj(E[p+x+y,c])
// Output contract (verified): float32 (B, 2, K), REAL PART ONLY.
//
// Champion skeleton (1 warp/batch, constexpr u|v table, direct coalesced
// stores, warp-sync only) with FP16 OPERAND STAGING: smem holds E as half
// precision, one 8-byte entry per position -> each of U/V/W is a single
// LDS.64 (8 B) instead of 16 B. Crossbar bytes in the k-loop halve
// (9216 -> 4608 B/batch). All arithmetic is fp32 after unpacking; only the
// input rounding (~3e-4 rms) enters the error budget (threshold 1e-3).
// ---------------------------------------------------------------------------

constexpr int K    = 173;
constexpr int WPB  = 8;     // warps (batches) per block
constexpr int ME   = 82;    // floats per batch per input array (41 pos * 2 c)
constexpr int NPOS = 41;
constexpr int PLN  = 48;    // padded positions per warp (uint2 entries)

struct Tab { unsigned short e[K]; };   // u | v<<8  (w = u+v-20 derived)

__host__ __device__ constexpr Tab make_tab() {
    Tab t{}; int cnt = 0;
    for (int m = -20; m <= 20; ++m) {
        for (int n = -20; n <= 20; ++n) {
            int am = m < 0 ? -m : m;
            int an = n < 0 ? -n : n;
            if (am * an <= 20 && n >= m && am + an <= 20) {
                t.e[cnt] = (unsigned short)((m + 20) | ((n + 20) << 8));
                ++cnt;
            }
        }
    }
    return t;
}

__device__ __forceinline__ float2 h2f(unsigned bits) {
    __half2 h = *reinterpret_cast<__half2*>(&bits);
    return __half22float2(h);
}

__global__ void __launch_bounds__(WPB * 32)
triplet_kernel(const float* __restrict__ er,
               const float* __restrict__ ei,
               float* __restrict__ out,
               int B)
{
    static constexpr Tab TAB = make_tab();

    // One uint2 (8 B) per position: (half2(re0,im0), half2(re1,im1)).
    __shared__ uint2 Esh[WPB][PLN];

    const int w    = threadIdx.x >> 5;
    const int lane = threadIdx.x & 31;
    const long long b = (long long)blockIdx.x * WPB + w;
    if (b >= B) return;

    // Stage: float2 reads give (c0, c1) per position from each input array.
    const float2* rb2 = reinterpret_cast<const float2*>(er + b * ME);
    const float2* ib2 = reinterpret_cast<const float2*>(ei + b * ME);
    #pragma unroll
    for (int j = lane; j < NPOS; j += 32) {
        const float2 r  = rb2[j];
        const float2 im = ib2[j];
        const __half2 lo = __floats2half2_rn(r.x, im.x);   // (re0, im0)
        const __half2 hi = __floats2half2_rn(r.y, im.y);   // (re1, im1)
        uint2 pack;
        pack.x = *reinterpret_cast<const unsigned*>(&lo);
        pack.y = *reinterpret_cast<const unsigned*>(&hi);
        Esh[w][j] = pack;
    }
    __syncwarp();

    const uint2* Eb = Esh[w];
    float* ob  = out + b * (2 * K);
    float* obK = ob + K;

    #pragma unroll
    for (int i = 0; i < 6; ++i) {
        const int k = lane + 32 * i;
        if (i < 5 || k < K) {              // iterations 0..4 unguarded
            const unsigned e = TAB.e[k];
            const int u  = e & 0xff;       // p + m
            const int v  = e >> 8;         // p + n
            const int ww = u + v - 20;     // p + m + n

            const uint2 Ur = Eb[u];        // one LDS.64 per operand
            const uint2 Vr = Eb[v];
            const uint2 Wr = Eb[ww];

            const float2 U0 = h2f(Ur.x), U1 = h2f(Ur.y);
            const float2 V0 = h2f(Vr.x), V1 = h2f(Vr.y);
            const float2 W0 = h2f(Wr.x), W1 = h2f(Wr.y);

            // S = sum_c U_c * conj(W_c)   (fp32)
            const float Sr = U0.x * W0.x + U0.y * W0.y + U1.x * W1.x + U1.y * W1.y;
            const float Si = U0.y * W0.x - U0.x * W0.y + U1.y * W1.x - U1.x * W1.y;

            float o0 = Sr * V0.x - Si * V0.y;
            float o1 = Sr * V1.x - Si * V1.y;

            if (u != v) {                  // symmetric term (m != n)
                const float Tr = V0.x * W0.x + V0.y * W0.y + V1.x * W1.x + V1.y * W1.y;
                const float Ti = V0.y * W0.x - V0.x * W0.y + V1.y * W1.x - V1.x * W1.y;
                o0 += Tr * U0.x - Ti * U0.y;
                o1 += Tr * U1.x - Ti * U1.y;
            }

            ob[k]  = o0;    // out[b, 0, k]
            obK[k] = o1;    // out[b, 1, k]
        }
    }
}

extern "C" void kernel_launch(void* const* d_in, const int* in_sizes, int n_in,
                              void* d_out, int out_size)
{
    const float* er = (const float*)d_in[0];   // E_real (B, 41, 2) float32
    const float* ei = (const float*)d_in[1];   // E_imag (B, 41, 2) float32
    float* out = (float*)d_out;                // float32 (B, 2, K) real parts

    const int B = in_sizes[0] / ME;
    const int grid = (B + WPB - 1) / WPB;

    triplet_kernel<<<grid, WPB * 32>>>(er, ei, out, B);
}

// round 15
// speedup vs baseline: 1.1309x; 1.0067x over previous
#include <cuda_runtime.h>
#include <cuda_fp16.h>
#include <cstdint>

// ---------------------------------------------------------------------------
// TripletFeatures: M=41, p=20.  Index set: |m*n|<=20, n>=m, |m|+|n|<=20, K=173.
// out[b,c,k] = Re( S_mn * E[p+n,c] ) + (m!=n) * Re( S_nm * E[p+m,c] )
//   with S_xy = sum_c E[p+x,c]*conj(E[p+x+y,c])
// Output contract (verified): float32 (B, 2, K), REAL PART ONLY.
//
// R14 champion (fp16 operand staging, fp32 math, 1 warp/batch, constexpr
// table, coalesced stores) + CROSS-WAVE L2 PREFETCH: each block prefetches
// the inputs of the block one wave ahead, so staging LDGs hit L2 (~250cyc)
// instead of DRAM (~577cyc). No registers, no smem, no occupancy cost.
// ---------------------------------------------------------------------------

constexpr int K    = 173;
constexpr int WPB  = 8;     // warps (batches) per block
constexpr int ME   = 82;    // floats per batch per input array (41 pos * 2 c)
constexpr int NPOS = 41;
constexpr int PLN  = 48;    // padded positions per warp (uint2 entries)
constexpr int PF_DIST = 1184;   // blocks per wave: 148 SM * 8 blocks/SM

struct Tab { unsigned short e[K]; };   // u | v<<8  (w = u+v-20 derived)

__host__ __device__ constexpr Tab make_tab() {
    Tab t{}; int cnt = 0;
    for (int m = -20; m <= 20; ++m) {
        for (int n = -20; n <= 20; ++n) {
            int am = m < 0 ? -m : m;
            int an = n < 0 ? -n : n;
            if (am * an <= 20 && n >= m && am + an <= 20) {
                t.e[cnt] = (unsigned short)((m + 20) | ((n + 20) << 8));
                ++cnt;
            }
        }
    }
    return t;
}

__device__ __forceinline__ float2 h2f(unsigned bits) {
    __half2 h = *reinterpret_cast<__half2*>(&bits);
    return __half22float2(h);
}

__global__ void __launch_bounds__(WPB * 32)
triplet_kernel(const float* __restrict__ er,
               const float* __restrict__ ei,
               float* __restrict__ out,
               int B)
{
    static constexpr Tab TAB = make_tab();

    // One uint2 (8 B) per position: (half2(re0,im0), half2(re1,im1)).
    __shared__ uint2 Esh[WPB][PLN];

    const int w    = threadIdx.x >> 5;
    const int lane = threadIdx.x & 31;
    const long long b = (long long)blockIdx.x * WPB + w;

    // ---- cross-wave L2 prefetch: inputs of the block one wave ahead -------
    {
        const long long pb = ((long long)blockIdx.x + PF_DIST) * WPB;
        if (pb + 9 <= B) {   // all prefetched lines provably in-bounds
            const int t = threadIdx.x;
            // 8 batches * 328 B = 2624 B per array -> 21 lines of 128 B
            if (t < 21) {
                const char* pa = (const char*)(er + pb * ME) + t * 128;
                asm volatile("prefetch.global.L2 [%0];" :: "l"(pa));
            } else if (t >= 32 && t < 53) {
                const char* pa = (const char*)(ei + pb * ME) + (t - 32) * 128;
                asm volatile("prefetch.global.L2 [%0];" :: "l"(pa));
            }
        }
    }

    if (b >= B) return;

    // Stage: float2 reads give (c0, c1) per position from each input array.
    const float2* rb2 = reinterpret_cast<const float2*>(er + b * ME);
    const float2* ib2 = reinterpret_cast<const float2*>(ei + b * ME);
    #pragma unroll
    for (int j = lane; j < NPOS; j += 32) {
        const float2 r  = rb2[j];
        const float2 im = ib2[j];
        const __half2 lo = __floats2half2_rn(r.x, im.x);   // (re0, im0)
        const __half2 hi = __floats2half2_rn(r.y, im.y);   // (re1, im1)
        uint2 pack;
        pack.x = *reinterpret_cast<const unsigned*>(&lo);
        pack.y = *reinterpret_cast<const unsigned*>(&hi);
        Esh[w][j] = pack;
    }
    __syncwarp();

    const uint2* Eb = Esh[w];
    float* ob  = out + b * (2 * K);
    float* obK = ob + K;

    #pragma unroll
    for (int i = 0; i < 6; ++i) {
        const int k = lane + 32 * i;
        if (i < 5 || k < K) {              // iterations 0..4 unguarded
            const unsigned e = TAB.e[k];
            const int u  = e & 0xff;       // p + m
            const int v  = e >> 8;         // p + n
            const int ww = u + v - 20;     // p + m + n

            const uint2 Ur = Eb[u];        // one LDS.64 per operand
            const uint2 Vr = Eb[v];
            const uint2 Wr = Eb[ww];

            const float2 U0 = h2f(Ur.x), U1 = h2f(Ur.y);
            const float2 V0 = h2f(Vr.x), V1 = h2f(Vr.y);
            const float2 W0 = h2f(Wr.x), W1 = h2f(Wr.y);

            // S = sum_c U_c * conj(W_c)   (fp32)
            const float Sr = U0.x * W0.x + U0.y * W0.y + U1.x * W1.x + U1.y * W1.y;
            const float Si = U0.y * W0.x - U0.x * W0.y + U1.y * W1.x - U1.x * W1.y;

            float o0 = Sr * V0.x - Si * V0.y;
            float o1 = Sr * V1.x - Si * V1.y;

            if (u != v) {                  // symmetric term (m != n)
                const float Tr = V0.x * W0.x + V0.y * W0.y + V1.x * W1.x + V1.y * W1.y;
                const float Ti = V0.y * W0.x - V0.x * W0.y + V1.y * W1.x - V1.x * W1.y;
                o0 += Tr * U0.x - Ti * U0.y;
                o1 += Tr * U1.x - Ti * U1.y;
            }

            ob[k]  = o0;    // out[b, 0, k]
            obK[k] = o1;    // out[b, 1, k]
        }
    }
}

extern "C" void kernel_launch(void* const* d_in, const int* in_sizes, int n_in,
                              void* d_out, int out_size)
{
    const float* er = (const float*)d_in[0];   // E_real (B, 41, 2) float32
    const float* ei = (const float*)d_in[1];   // E_imag (B, 41, 2) float32
    float* out = (float*)d_out;                // float32 (B, 2, K) real parts

    const int B = in_sizes[0] / ME;
    const int grid = (B + WPB - 1) / WPB;

    triplet_kernel<<<grid, WPB * 32>>>(er, ei, out, B);
}

// round 16
// speedup vs baseline: 1.3727x; 1.2138x over previous
#include <cuda_runtime.h>
#include <cuda_fp16.h>
#include <cstdint>

// ---------------------------------------------------------------------------
// TripletFeatures: M=41, p=20.  Index set: |m*n|<=20, n>=m, |m|+|n|<=20, K=173.
// out[b,c,k] = Re( S_mn * E[p+n,c] ) + (m!=n) * Re( S_nm * E[p+m,c] )
//   with S_xy = sum_c E[p+x,c]*conj(E[p+x+y,c])
// Output contract (verified): float32 (B, 2, K), REAL PART ONLY.
//
// BATCH-PAIRED FP16 SIMD: each warp handles 2 batches; every scalar in the
// k-loop is a half2 (val_b0, val_b1). HFMA2 does both batches per slot ->
// fma issue slots per batch nearly halve (24 -> 13); operand loads become
// one LDS.128 per operand per 2 batches; decode/guard amortize x2.
// All math fp16 (error budget ~6e-4 vs 1e-3 threshold; outputs cvt to f32).
// ---------------------------------------------------------------------------

constexpr int K    = 173;
constexpr int WPB  = 8;     // warps per block (each warp = 2 batches)
constexpr int ME   = 82;    // floats per batch per input array (41 pos * 2 c)
constexpr int NPOS = 41;
constexpr int PF_DIST = 740;   // blocks one wave ahead (148 SM * ~5 blocks)

struct Tab { unsigned short e[K]; };   // u | v<<8  (w = u+v-20 derived)

__host__ __device__ constexpr Tab make_tab() {
    Tab t{}; int cnt = 0;
    for (int m = -20; m <= 20; ++m) {
        for (int n = -20; n <= 20; ++n) {
            int am = m < 0 ? -m : m;
            int an = n < 0 ? -n : n;
            if (am * an <= 20 && n >= m && am + an <= 20) {
                t.e[cnt] = (unsigned short)((m + 20) | ((n + 20) << 8));
                ++cnt;
            }
        }
    }
    return t;
}

__device__ __forceinline__ __half2 H2(unsigned bits) {
    return *reinterpret_cast<__half2*>(&bits);
}
__device__ __forceinline__ unsigned U32(__half2 h) {
    return *reinterpret_cast<unsigned*>(&h);
}

__global__ void __launch_bounds__(WPB * 32, 5)
triplet_kernel(const float* __restrict__ er,
               const float* __restrict__ ei,
               float* __restrict__ out,
               int B)
{
    static constexpr Tab TAB = make_tab();

    // Per position, per warp: {h2(re0 b0,b1), h2(im0 b0,b1),
    //                          h2(re1 b0,b1), h2(im1 b0,b1)} = 16 B.
    __shared__ uint4 Esh[WPB][NPOS];

    const int w    = threadIdx.x >> 5;
    const int lane = threadIdx.x & 31;
    const long long pairI = (long long)blockIdx.x * WPB + w;
    const long long b0 = pairI * 2;

    // ---- cross-wave L2 prefetch (inputs of the block one wave ahead) ------
    {
        const long long pb = ((long long)blockIdx.x + PF_DIST) * (WPB * 2);
        if (pb + 17 <= B) {   // 16 batches + slack provably in-bounds
            const int t = threadIdx.x;
            // 16 batches * 328 B = 5248 B per array -> 41 lines of 128 B
            if (t < 41) {
                const char* pa = (const char*)(er + pb * ME) + t * 128;
                asm volatile("prefetch.global.L2 [%0];" :: "l"(pa));
            } else if (t >= 64 && t < 105) {
                const char* pa = (const char*)(ei + pb * ME) + (t - 64) * 128;
                asm volatile("prefetch.global.L2 [%0];" :: "l"(pa));
            }
        }
    }

    if (b0 >= B) return;
    const bool has_b1 = (b0 + 1 < B);
    const long long b1 = has_b1 ? b0 + 1 : b0;

    // ---- stage both batches (coalesced float2 reads) -----------------------
    const float2* rb0 = reinterpret_cast<const float2*>(er + b0 * ME);
    const float2* ib0 = reinterpret_cast<const float2*>(ei + b0 * ME);
    const float2* rb1 = reinterpret_cast<const float2*>(er + b1 * ME);
    const float2* ib1 = reinterpret_cast<const float2*>(ei + b1 * ME);
    #pragma unroll
    for (int j = lane; j < NPOS; j += 32) {
        const float2 r0 = rb0[j], i0 = ib0[j];
        const float2 r1 = rb1[j], i1 = ib1[j];
        uint4 pk;
        pk.x = U32(__floats2half2_rn(r0.x, r1.x));   // re comp0 (b0, b1)
        pk.y = U32(__floats2half2_rn(i0.x, i1.x));   // im comp0
        pk.z = U32(__floats2half2_rn(r0.y, r1.y));   // re comp1
        pk.w = U32(__floats2half2_rn(i0.y, i1.y));   // im comp1
        Esh[w][j] = pk;
    }
    __syncwarp();

    const uint4* Eb = Esh[w];
    float* o0b = out + b0 * (2 * K);
    float* o1b = out + b1 * (2 * K);

    #pragma unroll
    for (int i = 0; i < 6; ++i) {
        const int k = lane + 32 * i;
        if (i < 5 || k < K) {              // iterations 0..4 unguarded
            const unsigned e = TAB.e[k];
            const int u  = e & 0xff;       // p + m
            const int v  = e >> 8;         // p + n
            const int ww = u + v - 20;     // p + m + n

            const uint4 Uq = Eb[u];        // one LDS.128 per operand
            const uint4 Vq = Eb[v];
            const uint4 Wq = Eb[ww];

            const __half2 URe0 = H2(Uq.x), UIm0 = H2(Uq.y);
            const __half2 URe1 = H2(Uq.z), UIm1 = H2(Uq.w);
            const __half2 VRe0 = H2(Vq.x), VIm0 = H2(Vq.y);
            const __half2 VRe1 = H2(Vq.z), VIm1 = H2(Vq.w);
            const __half2 WRe0 = H2(Wq.x), WIm0 = H2(Wq.y);
            const __half2 WRe1 = H2(Wq.z), WIm1 = H2(Wq.w);

            // Sr = ur0*wr0 + ui0*wi0 + ur1*wr1 + ui1*wi1   (per batch lane)
            const __half2 Sr =
                __hfma2(UIm1, WIm1, __hfma2(URe1, WRe1,
                __hfma2(UIm0, WIm0, __hmul2(URe0, WRe0))));
            // nSi = -Si = ur0*wi0 - ui0*wr0 + ur1*wi1 - ui1*wr1
            const __half2 t1 = __hfma2(URe1, WIm1, __hmul2(URe0, WIm0));
            const __half2 t2 = __hfma2(UIm1, WRe1, __hmul2(UIm0, WRe0));
            const __half2 nSi = __hsub2(t1, t2);

            // o_c = Sr*vr_c + nSi*vi_c
            __half2 O0 = __hfma2(nSi, VIm0, __hmul2(Sr, VRe0));
            __half2 O1 = __hfma2(nSi, VIm1, __hmul2(Sr, VRe1));

            if (u != v) {                  // symmetric term (m != n)
                const __half2 Tr =
                    __hfma2(VIm1, WIm1, __hfma2(VRe1, WRe1,
                    __hfma2(VIm0, WIm0, __hmul2(VRe0, WRe0))));
                const __half2 s1 = __hfma2(VRe1, WIm1, __hmul2(VRe0, WIm0));
                const __half2 s2 = __hfma2(VIm1, WRe1, __hmul2(VIm0, WRe0));
                const __half2 nTi = __hsub2(s1, s2);
                O0 = __hfma2(nTi, UIm0, __hfma2(Tr, URe0, O0));
                O1 = __hfma2(nTi, UIm1, __hfma2(Tr, URe1, O1));
            }

            const float2 f0 = __half22float2(O0);   // (o0_b0, o0_b1)
            const float2 f1 = __half22float2(O1);   // (o1_b0, o1_b1)

            o0b[k]     = f0.x;    // out[b0, 0, k]
            o0b[K + k] = f1.x;    // out[b0, 1, k]
            if (has_b1) {
                o1b[k]     = f0.y;    // out[b1, 0, k]
                o1b[K + k] = f1.y;    // out[b1, 1, k]
            }
        }
    }
}

extern "C" void kernel_launch(void* const* d_in, const int* in_sizes, int n_in,
                              void* d_out, int out_size)
{
    const float* er = (const float*)d_in[0];   // E_real (B, 41, 2) float32
    const float* ei = (const float*)d_in[1];   // E_imag (B, 41, 2) float32
    float* out = (float*)d_out;                // float32 (B, 2, K) real parts

    const int B = in_sizes[0] / ME;
    const long long npairs = (B + 1) / 2;
    const int grid = (int)((npairs + WPB - 1) / WPB);

    triplet_kernel<<<grid, WPB * 32>>>(er, ei, out, B);
}

// round 17
// speedup vs baseline: 1.3824x; 1.0071x over previous
#include <cuda_runtime.h>
#include <cuda_fp16.h>
#include <cstdint>

// ---------------------------------------------------------------------------
// TripletFeatures: M=41, p=20.  Index set: |m*n|<=20, n>=m, |m|+|n|<=20, K=173.
// out[b,c,k] = Re( S_mn * E[p+n,c] ) + (m!=n) * Re( S_nm * E[p+m,c] )
//   with S_xy = sum_c E[p+x,c]*conj(E[p+x+y,c])
// Output contract (verified): float32 (B, 2, K), REAL PART ONLY.
//
// BATCH-PAIRED FP16 SIMD (R16 champion) + register slimming: all b1
// addressing folded into constant offsets from b0 pointers, minblocks=6
// -> 75% occupancy (was 55.8% at 48 regs / 5 blocks).
// ---------------------------------------------------------------------------

constexpr int K    = 173;
constexpr int WPB  = 8;     // warps per block (each warp = 2 batches)
constexpr int ME   = 82;    // floats per batch per input array (41 pos * 2 c)
constexpr int NPOS = 41;
constexpr int PF_DIST = 888;   // blocks one wave ahead (148 SM * 6 blocks)

struct Tab { unsigned short e[K]; };   // u | v<<8  (w = u+v-20 derived)

__host__ __device__ constexpr Tab make_tab() {
    Tab t{}; int cnt = 0;
    for (int m = -20; m <= 20; ++m) {
        for (int n = -20; n <= 20; ++n) {
            int am = m < 0 ? -m : m;
            int an = n < 0 ? -n : n;
            if (am * an <= 20 && n >= m && am + an <= 20) {
                t.e[cnt] = (unsigned short)((m + 20) | ((n + 20) << 8));
                ++cnt;
            }
        }
    }
    return t;
}

__device__ __forceinline__ __half2 H2(unsigned bits) {
    return *reinterpret_cast<__half2*>(&bits);
}
__device__ __forceinline__ unsigned U32(__half2 h) {
    return *reinterpret_cast<unsigned*>(&h);
}

__global__ void __launch_bounds__(WPB * 32, 6)
triplet_kernel(const float* __restrict__ er,
               const float* __restrict__ ei,
               float* __restrict__ out,
               int B)
{
    static constexpr Tab TAB = make_tab();

    // Per position, per warp: {h2(re0 b0,b1), h2(im0 b0,b1),
    //                          h2(re1 b0,b1), h2(im1 b0,b1)} = 16 B.
    __shared__ uint4 Esh[WPB][NPOS];

    const int w    = threadIdx.x >> 5;
    const int lane = threadIdx.x & 31;
    const long long b0 = ((long long)blockIdx.x * WPB + w) * 2;

    // ---- cross-wave L2 prefetch (inputs of the block one wave ahead) ------
    {
        const long long pb = ((long long)blockIdx.x + PF_DIST) * (WPB * 2);
        if (pb + 17 <= B) {
            const int t = threadIdx.x;
            // 16 batches * 328 B = 5248 B per array -> 41 lines of 128 B
            if (t < 41) {
                const char* pa = (const char*)(er + pb * ME) + t * 128;
                asm volatile("prefetch.global.L2 [%0];" :: "l"(pa));
            } else if (t >= 64 && t < 105) {
                const char* pa = (const char*)(ei + pb * ME) + (t - 64) * 128;
                asm volatile("prefetch.global.L2 [%0];" :: "l"(pa));
            }
        }
    }

    if (b0 >= B) return;
    const bool has_b1 = (b0 + 1 < B);
    // b1 pointer offsets (float2 units for inputs, floats for output):
    const int di = has_b1 ? NPOS : 0;        // +41 float2 = next batch

    // ---- stage both batches (coalesced float2 reads) -----------------------
    const float2* rb0 = reinterpret_cast<const float2*>(er + b0 * ME);
    const float2* ib0 = reinterpret_cast<const float2*>(ei + b0 * ME);
    #pragma unroll
    for (int j = lane; j < NPOS; j += 32) {
        const float2 r0 = rb0[j],      i0 = ib0[j];
        const float2 r1 = rb0[j + di], i1 = ib0[j + di];
        uint4 pk;
        pk.x = U32(__floats2half2_rn(r0.x, r1.x));   // re comp0 (b0, b1)
        pk.y = U32(__floats2half2_rn(i0.x, i1.x));   // im comp0
        pk.z = U32(__floats2half2_rn(r0.y, r1.y));   // re comp1
        pk.w = U32(__floats2half2_rn(i0.y, i1.y));   // im comp1
        Esh[w][j] = pk;
    }
    __syncwarp();

    const uint4* Eb = Esh[w];
    float* ob = out + b0 * (2 * K);      // single base pointer
    const int d1 = has_b1 ? 2 * K : 0;   // b1 row offset (floats)

    #pragma unroll
    for (int i = 0; i < 6; ++i) {
        const int k = lane + 32 * i;
        if (i < 5 || k < K) {              // iterations 0..4 unguarded
            const unsigned e = TAB.e[k];
            const int u  = e & 0xff;       // p + m
            const int v  = e >> 8;         // p + n
            const int ww = u + v - 20;     // p + m + n

            const uint4 Uq = Eb[u];        // one LDS.128 per operand
            const uint4 Vq = Eb[v];
            const uint4 Wq = Eb[ww];

            const __half2 URe0 = H2(Uq.x), UIm0 = H2(Uq.y);
            const __half2 URe1 = H2(Uq.z), UIm1 = H2(Uq.w);
            const __half2 VRe0 = H2(Vq.x), VIm0 = H2(Vq.y);
            const __half2 VRe1 = H2(Vq.z), VIm1 = H2(Vq.w);
            const __half2 WRe0 = H2(Wq.x), WIm0 = H2(Wq.y);
            const __half2 WRe1 = H2(Wq.z), WIm1 = H2(Wq.w);

            // Sr = sum_c Re(U_c * conj(W_c))   (per batch half2 lane)
            const __half2 Sr =
                __hfma2(UIm1, WIm1, __hfma2(URe1, WRe1,
                __hfma2(UIm0, WIm0, __hmul2(URe0, WRe0))));
            // nSi = -Im(S)
            const __half2 t1 = __hfma2(URe1, WIm1, __hmul2(URe0, WIm0));
            const __half2 t2 = __hfma2(UIm1, WRe1, __hmul2(UIm0, WRe0));
            const __half2 nSi = __hsub2(t1, t2);

            __half2 O0 = __hfma2(nSi, VIm0, __hmul2(Sr, VRe0));
            __half2 O1 = __hfma2(nSi, VIm1, __hmul2(Sr, VRe1));

            if (u != v) {                  // symmetric term (m != n)
                const __half2 Tr =
                    __hfma2(VIm1, WIm1, __hfma2(VRe1, WRe1,
                    __hfma2(VIm0, WIm0, __hmul2(VRe0, WRe0))));
                const __half2 s1 = __hfma2(VRe1, WIm1, __hmul2(VRe0, WIm0));
                const __half2 s2 = __hfma2(VIm1, WRe1, __hmul2(VIm0, WRe0));
                const __half2 nTi = __hsub2(s1, s2);
                O0 = __hfma2(nTi, UIm0, __hfma2(Tr, URe0, O0));
                O1 = __hfma2(nTi, UIm1, __hfma2(Tr, URe1, O1));
            }

            const float2 f0 = __half22float2(O0);   // (o0_b0, o0_b1)
            const float2 f1 = __half22float2(O1);   // (o1_b0, o1_b1)

            ob[k]          = f0.x;    // out[b0, 0, k]
            ob[K + k]      = f1.x;    // out[b0, 1, k]
            if (has_b1) {
                ob[d1 + k]     = f0.y;    // out[b1, 0, k]
                ob[d1 + K + k] = f1.y;    // out[b1, 1, k]
            }
        }
    }
}

extern "C" void kernel_launch(void* const* d_in, const int* in_sizes, int n_in,
                              void* d_out, int out_size)
{
    const float* er = (const float*)d_in[0];   // E_real (B, 41, 2) float32
    const float* ei = (const float*)d_in[1];   // E_imag (B, 41, 2) float32
    float* out = (float*)d_out;                // float32 (B, 2, K) real parts

    const int B = in_sizes[0] / ME;
    const long long npairs = (B + 1) / 2;
    const int grid = (int)((npairs + WPB - 1) / WPB);

    triplet_kernel<<<grid, WPB * 32>>>(er, ei, out, B);
}